// round 6
// baseline (speedup 1.0000x reference)
#include <cuda_runtime.h>
#include <cuda_fp16.h>
#include <cstdint>

typedef unsigned long long ull;

#define Bb   2
#define Nn   512
#define Hh   1024
#define HDd  512
#define Mm   1024          // B*N rows
#define NTOT 1536          // fused GEMM output columns

// GEMM tiling
#define BM 128
#define BN 64
#define BK 64
#define KT (Hh / BK)             // 16 k-tiles
#define STG 24576                // A(16KB)+B(8KB) per stage
#define EP_PITCH 66              // epilogue smem pitch (floats)
#define GEMM_SMEM (2 * STG)      // 49152 >= 128*66*4 = 33792

// end kernel smem: W(4KB) + A 2x16KB + C 2x8KB = 53248
#define END_SMEM ((1024 + 2 * 4096 + 2 * 2048) * 4)

// -------- scratch --------
__device__ __half g_Ah[Mm * Hh];            // emb in fp16
__device__ __half g_Bh[NTOT * Hh];          // weights transposed [n][k], fp16
__device__ float  g_aD[HDd * 2 * Mm];       // (emb@W1_start + b_e1)^T duplicated: [d][2m]=(v,v)
__device__ float  g_cT[HDd * Mm];           // (emb@W1_end)^T  [d][m]

// -------- PTX helpers --------
__device__ __forceinline__ uint32_t smem_u32(const void* p) {
    uint32_t a;
    asm("{ .reg .u64 t; cvta.to.shared.u64 t, %1; cvt.u32.u64 %0, t; }" : "=r"(a) : "l"(p));
    return a;
}
#define CP16(dst, src) \
    asm volatile("cp.async.cg.shared.global [%0], [%1], 16;" :: "r"(dst), "l"(src) : "memory")
#define CP_COMMIT() asm volatile("cp.async.commit_group;" ::: "memory")

#define LDSM4(r0, r1, r2, r3, a) \
    asm volatile("ldmatrix.sync.aligned.m8n8.x4.shared.b16 {%0,%1,%2,%3}, [%4];" \
        : "=r"(r0), "=r"(r1), "=r"(r2), "=r"(r3) : "r"(a))

#define MMA16816(d, a0, a1, a2, a3, b0, b1) \
    asm volatile("mma.sync.aligned.m16n8k16.row.col.f32.f16.f16.f32 " \
        "{%0,%1,%2,%3}, {%4,%5,%6,%7}, {%8,%9}, {%0,%1,%2,%3};" \
        : "+f"((d)[0]), "+f"((d)[1]), "+f"((d)[2]), "+f"((d)[3]) \
        : "r"(a0), "r"(a1), "r"(a2), "r"(a3), "r"(b0), "r"(b1))

// -------- prepass: emb -> fp16, plus start-logit output init --------
__global__ __launch_bounds__(256) void esplit_kernel(const float* __restrict__ emb,
                                                     const float* __restrict__ b_s2,
                                                     float* __restrict__ out) {
    int i = blockIdx.x * 256 + threadIdx.x;        // float4 index, 262144 total
    float4 v = ((const float4*)emb)[i];
    __half2* A = (__half2*)g_Ah;
    A[2 * i]     = __floats2half2_rn(v.x, v.y);
    A[2 * i + 1] = __floats2half2_rn(v.z, v.w);
    if (i < Mm) out[i] = b_s2[0];
}

// -------- prepass: transpose weights -> g_Bh[n][k] fp16 --------
__global__ __launch_bounds__(256) void wsplit_kernel(const float* __restrict__ W_s1,
                                                     const float* __restrict__ W_e1) {
    __shared__ float sm[32][33];
    const int n0 = blockIdx.x * 32, k0 = blockIdx.y * 32;
    const int t = threadIdx.x, c = t & 31, r = t >> 5;
#pragma unroll
    for (int p = 0; p < 4; p++) {
        int k = k0 + r + 8 * p, n = n0 + c;
        float v;
        if (n < 512)       v = W_s1[(size_t)k * 512 + n];
        else if (n < 1024) v = W_e1[(size_t)k * 512 + (n - 512)];
        else               v = W_e1[(size_t)(1024 + k) * 512 + (n - 1024)];
        sm[r + 8 * p][c] = v;   // sm[k_local][n_local]
    }
    __syncthreads();
#pragma unroll
    for (int p = 0; p < 4; p++) {
        int ln = r + 8 * p, lk = c;
        g_Bh[(size_t)(n0 + ln) * Hh + k0 + lk] = __float2half_rn(sm[lk][ln]);
    }
}

// -------- HMMA GEMM: C[1024,1536] = emb_fp16 @ [W_s1|W_e1a|W_e1b]_fp16 --------
__device__ __forceinline__ void load_stage(uint32_t abase, const __half* __restrict__ A,
                                           const __half* __restrict__ B, int kt, int tid) {
    const uint32_t bbase = abase + 16384;
#pragma unroll
    for (int i = 0; i < 4; i++) {
        int c = tid + i * 256;             // 1024 16B chunks for A (128 rows x 8)
        int row = c >> 3, kc = c & 7;
        uint32_t dst = abase + (uint32_t)(row * 128) + (uint32_t)((kc ^ (row & 7)) << 4);
        CP16(dst, A + (size_t)row * Hh + kt * BK + kc * 8);
    }
#pragma unroll
    for (int i = 0; i < 2; i++) {
        int c = tid + i * 256;             // 512 chunks for B (64 rows x 8)
        int row = c >> 3, kc = c & 7;
        uint32_t dst = bbase + (uint32_t)(row * 128) + (uint32_t)((kc ^ (row & 7)) << 4);
        CP16(dst, B + (size_t)row * Hh + kt * BK + kc * 8);
    }
}

__global__ __launch_bounds__(256, 2) void gemm_kernel(
    const float* __restrict__ b_s1, const float* __restrict__ w_s2,
    const float* __restrict__ b_e1, float* __restrict__ out)
{
    extern __shared__ char smem[];
    const uint32_t sb = smem_u32(smem);

    const int tid = threadIdx.x, lane = tid & 31, wid = tid >> 5;
    const int wm = wid & 3;                 // warp row group (32 rows)
    const int wn = wid >> 2;                // warp col group (32 cols)
    const int m0 = blockIdx.y * BM;
    const int n0 = blockIdx.x * BN;
    const __half* Ap = g_Ah + (size_t)m0 * Hh;
    const __half* Bp = g_Bh + (size_t)n0 * Hh;

    float acc[2][4][4];
#pragma unroll
    for (int i = 0; i < 2; i++)
#pragma unroll
        for (int j = 0; j < 4; j++)
#pragma unroll
            for (int r = 0; r < 4; r++) acc[i][j][r] = 0.f;

    const int a_row = wm * 32 + (lane & 15);
    const int b_rowb = wn * 32 + (lane & 15);
    const int l_kc  = lane >> 4;

    load_stage(sb, Ap, Bp, 0, tid);
    CP_COMMIT();

    for (int t = 0; t < KT; t++) {
        if (t + 1 < KT) {
            load_stage(sb + (uint32_t)(((t + 1) & 1) * STG), Ap, Bp, t + 1, tid);
            CP_COMMIT();
            asm volatile("cp.async.wait_group 1;" ::: "memory");
        } else {
            asm volatile("cp.async.wait_group 0;" ::: "memory");
        }
        __syncthreads();

        const uint32_t Ab = sb + (uint32_t)((t & 1) * STG);
        const uint32_t Bbs = Ab + 16384;
#pragma unroll
        for (int ks = 0; ks < 4; ks++) {              // 4 k16-steps in BK=64
            const int kc = 2 * ks + l_kc;
            uint32_t a0r[4], a1r[4];
            {
                int r = a_row;
                LDSM4(a0r[0], a0r[1], a0r[2], a0r[3],
                      Ab + (uint32_t)(r * 128) + (uint32_t)((kc ^ (r & 7)) << 4));
                r = a_row + 16;
                LDSM4(a1r[0], a1r[1], a1r[2], a1r[3],
                      Ab + (uint32_t)(r * 128) + (uint32_t)((kc ^ (r & 7)) << 4));
            }
#pragma unroll
            for (int jg = 0; jg < 2; jg++) {          // 2 n16-groups = 4 n8-tiles
                int r = b_rowb + 16 * jg;
                uint32_t b0, b1, b2, b3;
                LDSM4(b0, b1, b2, b3,
                      Bbs + (uint32_t)(r * 128) + (uint32_t)((kc ^ (r & 7)) << 4));
                MMA16816(acc[0][2 * jg],     a0r[0], a0r[1], a0r[2], a0r[3], b0, b2);
                MMA16816(acc[0][2 * jg + 1], a0r[0], a0r[1], a0r[2], a0r[3], b1, b3);
                MMA16816(acc[1][2 * jg],     a1r[0], a1r[1], a1r[2], a1r[3], b0, b2);
                MMA16816(acc[1][2 * jg + 1], a1r[0], a1r[1], a1r[2], a1r[3], b1, b3);
            }
        }
        __syncthreads();
    }

    // ---- dump accumulators to smem [BM][EP_PITCH] ----
    float* eps = (float*)smem;
    const int rbase = wm * 32 + (lane >> 2);
    const int cbase = wn * 32 + (lane & 3) * 2;
#pragma unroll
    for (int i = 0; i < 2; i++)
#pragma unroll
        for (int j = 0; j < 4; j++) {
            int rr = rbase + i * 16;
            int cc = cbase + j * 8;
            *(float2*)&eps[rr * EP_PITCH + cc]       = make_float2(acc[i][j][0], acc[i][j][1]);
            *(float2*)&eps[(rr + 8) * EP_PITCH + cc] = make_float2(acc[i][j][2], acc[i][j][3]);
        }
    __syncthreads();

    // ---- epilogue ----
    const int blk = n0 >> 9;                 // 0 / 1 / 2
    const int cb  = n0 & 511;
    if (blk == 0) {
        const int r = tid >> 1, h = tid & 1;
        float s = 0.f;
#pragma unroll 8
        for (int c = 0; c < 32; c++) {
            int d = cb + h * 32 + c;
            s += fmaxf(eps[r * EP_PITCH + h * 32 + c] + __ldg(b_s1 + d), 0.f) * __ldg(w_s2 + d);
        }
        s += __shfl_xor_sync(0xffffffffu, s, 1);
        if (h == 0) atomicAdd(out + m0 + r, s);
    } else if (blk == 1) {
#pragma unroll 4
        for (int it = 0; it < 32; it++) {
            int idx = it * 256 + tid;            // 8192 = 128m x 64d
            int m = idx & 127, dl = idx >> 7;
            int d = cb + dl;
            float v = eps[m * EP_PITCH + dl] + __ldg(b_e1 + d);
            *(float2*)(g_aD + (size_t)d * (2 * Mm) + 2 * (m0 + m)) = make_float2(v, v);
        }
    } else {
#pragma unroll 4
        for (int it = 0; it < 32; it++) {
            int idx = it * 256 + tid;
            int m = idx & 127, dl = idx >> 7;
            g_cT[(size_t)(cb + dl) * Mm + m0 + m] = eps[m * EP_PITCH + dl];
        }
    }
}

// -------- end logits: packed f32x2 relu-reduction, cp.async pipelined --------
// acc pair = (result for j0, result for j1): aDup=(a,a), cPair=(c0,c1)
#define RELUFMA(acc, a2, c2, w2) \
    asm("{\n\t.reg .f32 lo, hi; .reg .b64 s, m;\n\t" \
        "add.rn.f32x2 s, %1, %2;\n\t" \
        "mov.b64 {lo, hi}, s;\n\t" \
        "max.f32 lo, lo, 0f00000000;\n\t" \
        "max.f32 hi, hi, 0f00000000;\n\t" \
        "mov.b64 m, {lo, hi};\n\t" \
        "fma.rn.f32x2 %0, m, %3, %0;\n\t}" \
        : "+l"(acc) : "l"(a2), "l"(c2), "l"(w2))

__global__ __launch_bounds__(512) void end_kernel(
    const float* __restrict__ w_e2, const float* __restrict__ b_e2,
    float* __restrict__ out_end)
{
    extern __shared__ float sf[];
    // layout (floats): W dup [1024] | A stages [2][4096] | C stages [2][2048]
    float2* Wsm = (float2*)sf;
    const uint32_t sb = smem_u32(sf);
    const uint32_t AOFF = 1024 * 4;
    const uint32_t COFF = AOFF + 2 * 4096 * 4;

    const int t = threadIdx.x;
    const int bz = blockIdx.z;
    const int i0 = blockIdx.y * 64, j0 = blockIdx.x * 64;
    const int mi = bz * Nn + i0, mj = bz * Nn + j0;

    if (t < 512) { float w = w_e2[t]; Wsm[t] = make_float2(w, w); }

    const int tx = t & 31;          // j-group: 2 j at tx*2
    const int ty = t >> 5;          // i-group: 4 i at ty*4

    const float* Asrc0 = g_aD + 2 * mi;
    const float* Csrc0 = g_cT + mj;

    ull acc[4];
#pragma unroll
    for (int a = 0; a < 4; a++) acc[a] = 0;

#define LOAD_CHUNK(ch) do { \
    const int _st = (ch) & 1; \
    const uint32_t _Ab = sb + AOFF + (uint32_t)(_st * 4096 * 4); \
    const uint32_t _Cb = sb + COFF + (uint32_t)(_st * 2048 * 4); \
    const float* _As = Asrc0 + (size_t)((ch) * 32) * 2048; \
    const float* _Cs = Csrc0 + (size_t)((ch) * 32) * 1024; \
    _Pragma("unroll") \
    for (int _i = 0; _i < 2; _i++) { \
        int _c = t + _i * 512; \
        int _r = _c >> 5, _q = _c & 31; \
        CP16(_Ab + (uint32_t)(_r * 512 + _q * 16), _As + (size_t)_r * 2048 + _q * 4); \
    } \
    { \
        int _r = t >> 4, _q = t & 15; \
        CP16(_Cb + (uint32_t)(_r * 256 + _q * 16), _Cs + (size_t)_r * 1024 + _q * 4); \
    } \
} while (0)

    LOAD_CHUNK(0);
    CP_COMMIT();

    for (int ch = 0; ch < 16; ch++) {
        if (ch + 1 < 16) {
            LOAD_CHUNK(ch + 1);
            CP_COMMIT();
            asm volatile("cp.async.wait_group 1;" ::: "memory");
        } else {
            asm volatile("cp.async.wait_group 0;" ::: "memory");
        }
        __syncthreads();

        const int st = ch & 1;
        const float* Abuf = sf + 1024 + st * 4096;
        const float* Cbuf = sf + 1024 + 2 * 4096 + st * 2048;
#pragma unroll 8
        for (int dc = 0; dc < 32; dc++) {
            ull w2 = *(const ull*)&Wsm[ch * 32 + dc];
            const float* ar = Abuf + dc * 128 + ty * 8;
            ulonglong2 aP0 = *(const ulonglong2*)ar;          // dup pairs (i0),(i1)
            ulonglong2 aP1 = *(const ulonglong2*)(ar + 4);    // dup pairs (i2),(i3)
            ull cP = *(const ull*)(Cbuf + dc * 64 + tx * 2);  // (c0,c1)
            RELUFMA(acc[0], aP0.x, cP, w2);
            RELUFMA(acc[1], aP0.y, cP, w2);
            RELUFMA(acc[2], aP1.x, cP, w2);
            RELUFMA(acc[3], aP1.y, cP, w2);
        }
        __syncthreads();
    }

    const float be = b_e2[0];
#pragma unroll
    for (int i = 0; i < 4; i++) {
        float l0, h0;
        asm("mov.b64 {%0, %1}, %2;" : "=f"(l0), "=f"(h0) : "l"(acc[i]));
        size_t r0 = (size_t)bz * Nn * Nn + (size_t)(i0 + ty * 4 + i) * Nn + j0 + tx * 2;
        *(float2*)(out_end + r0) = make_float2(l0 + be, h0 + be);
    }
}

// -------- host --------
extern "C" void kernel_launch(void* const* d_in, const int* in_sizes, int n_in,
                              void* d_out, int out_size)
{
    (void)in_sizes; (void)n_in; (void)out_size;
    const float* emb  = (const float*)d_in[0];
    const float* W_s1 = (const float*)d_in[1];
    const float* b_s1 = (const float*)d_in[2];
    const float* w_s2 = (const float*)d_in[3];
    const float* b_s2 = (const float*)d_in[4];
    const float* W_e1 = (const float*)d_in[5];
    const float* b_e1 = (const float*)d_in[6];
    const float* w_e2 = (const float*)d_in[7];
    const float* b_e2 = (const float*)d_in[8];
    float* out = (float*)d_out;

    static bool attr_done = false;
    if (!attr_done) {
        cudaFuncSetAttribute(gemm_kernel, cudaFuncAttributeMaxDynamicSharedMemorySize, GEMM_SMEM);
        cudaFuncSetAttribute(end_kernel, cudaFuncAttributeMaxDynamicSharedMemorySize, END_SMEM);
        attr_done = true;
    }

    esplit_kernel<<<(Mm * Hh / 4) / 256, 256>>>(emb, b_s2, out);
    wsplit_kernel<<<dim3(NTOT / 32, Hh / 32), 256>>>(W_s1, W_e1);

    dim3 gg(NTOT / BN, Mm / BM);                  // 24 x 8 = 192 CTAs
    gemm_kernel<<<gg, 256, GEMM_SMEM>>>(b_s1, w_s2, b_e1, out);

    dim3 ge(Nn / 64, Nn / 64, Bb);                // 8 x 8 x 2 = 128 CTAs
    end_kernel<<<ge, 512, END_SMEM>>>(w_e2, b_e2, out + Mm);
}

// round 7
// speedup vs baseline: 1.0618x; 1.0618x over previous
#include <cuda_runtime.h>
#include <cuda_fp16.h>
#include <cstdint>

typedef unsigned long long ull;

#define Bb   2
#define Nn   512
#define Hh   1024
#define HDd  512
#define Mm   1024          // B*N rows
#define NTOT 1536          // fused GEMM output columns

// GEMM tiling
#define BM 128
#define BN 64
#define BK 64
#define KT (Hh / BK)             // 16 k-tiles
#define STG 24576                // A(16KB)+B(8KB) per stage
#define EP_PITCH 66              // epilogue smem pitch (floats)
#define GEMM_SMEM (2 * STG)      // 49152 >= 128*66*4 = 33792

// end kernel smem (floats): W dup 1024 | per half: A 2x4096 + C 2x2048 (=12288)
#define END_SMEM ((1024 + 2 * 12288) * 4)   // 102400 bytes

// -------- scratch --------
__device__ __half g_Ah[Mm * Hh];            // emb in fp16
__device__ __half g_Bh[NTOT * Hh];          // weights transposed [n][k], fp16
__device__ float  g_aD[HDd * 2 * Mm];       // (emb@W1_start + b_e1)^T duplicated: [d][2m]=(v,v)
__device__ float  g_cT[HDd * Mm];           // (emb@W1_end)^T  [d][m]

// -------- PTX helpers --------
__device__ __forceinline__ uint32_t smem_u32(const void* p) {
    uint32_t a;
    asm("{ .reg .u64 t; cvta.to.shared.u64 t, %1; cvt.u32.u64 %0, t; }" : "=r"(a) : "l"(p));
    return a;
}
#define CP16(dst, src) \
    asm volatile("cp.async.cg.shared.global [%0], [%1], 16;" :: "r"(dst), "l"(src) : "memory")
#define CP_COMMIT() asm volatile("cp.async.commit_group;" ::: "memory")

#define LDSM4(r0, r1, r2, r3, a) \
    asm volatile("ldmatrix.sync.aligned.m8n8.x4.shared.b16 {%0,%1,%2,%3}, [%4];" \
        : "=r"(r0), "=r"(r1), "=r"(r2), "=r"(r3) : "r"(a))

#define MMA16816(d, a0, a1, a2, a3, b0, b1) \
    asm volatile("mma.sync.aligned.m16n8k16.row.col.f32.f16.f16.f32 " \
        "{%0,%1,%2,%3}, {%4,%5,%6,%7}, {%8,%9}, {%0,%1,%2,%3};" \
        : "+f"((d)[0]), "+f"((d)[1]), "+f"((d)[2]), "+f"((d)[3]) \
        : "r"(a0), "r"(a1), "r"(a2), "r"(a3), "r"(b0), "r"(b1))

// -------- prepass: emb -> fp16, plus start-logit output init --------
__global__ __launch_bounds__(256) void esplit_kernel(const float* __restrict__ emb,
                                                     const float* __restrict__ b_s2,
                                                     float* __restrict__ out) {
    int i = blockIdx.x * 256 + threadIdx.x;        // float4 index, 262144 total
    float4 v = ((const float4*)emb)[i];
    __half2* A = (__half2*)g_Ah;
    A[2 * i]     = __floats2half2_rn(v.x, v.y);
    A[2 * i + 1] = __floats2half2_rn(v.z, v.w);
    if (i < Mm) out[i] = b_s2[0];
}

// -------- prepass: transpose weights -> g_Bh[n][k] fp16 --------
__global__ __launch_bounds__(256) void wsplit_kernel(const float* __restrict__ W_s1,
                                                     const float* __restrict__ W_e1) {
    __shared__ float sm[32][33];
    const int n0 = blockIdx.x * 32, k0 = blockIdx.y * 32;
    const int t = threadIdx.x, c = t & 31, r = t >> 5;
#pragma unroll
    for (int p = 0; p < 4; p++) {
        int k = k0 + r + 8 * p, n = n0 + c;
        float v;
        if (n < 512)       v = W_s1[(size_t)k * 512 + n];
        else if (n < 1024) v = W_e1[(size_t)k * 512 + (n - 512)];
        else               v = W_e1[(size_t)(1024 + k) * 512 + (n - 1024)];
        sm[r + 8 * p][c] = v;   // sm[k_local][n_local]
    }
    __syncthreads();
#pragma unroll
    for (int p = 0; p < 4; p++) {
        int ln = r + 8 * p, lk = c;
        g_Bh[(size_t)(n0 + ln) * Hh + k0 + lk] = __float2half_rn(sm[lk][ln]);
    }
}

// -------- HMMA GEMM: C[1024,1536] = emb_fp16 @ [W_s1|W_e1a|W_e1b]_fp16 --------
__device__ __forceinline__ void load_stage(uint32_t abase, const __half* __restrict__ A,
                                           const __half* __restrict__ B, int kt, int tid) {
    const uint32_t bbase = abase + 16384;
#pragma unroll
    for (int i = 0; i < 4; i++) {
        int c = tid + i * 256;             // 1024 16B chunks for A (128 rows x 8)
        int row = c >> 3, kc = c & 7;
        uint32_t dst = abase + (uint32_t)(row * 128) + (uint32_t)((kc ^ (row & 7)) << 4);
        CP16(dst, A + (size_t)row * Hh + kt * BK + kc * 8);
    }
#pragma unroll
    for (int i = 0; i < 2; i++) {
        int c = tid + i * 256;             // 512 chunks for B (64 rows x 8)
        int row = c >> 3, kc = c & 7;
        uint32_t dst = bbase + (uint32_t)(row * 128) + (uint32_t)((kc ^ (row & 7)) << 4);
        CP16(dst, B + (size_t)row * Hh + kt * BK + kc * 8);
    }
}

__global__ __launch_bounds__(256, 2) void gemm_kernel(
    const float* __restrict__ b_s1, const float* __restrict__ w_s2,
    const float* __restrict__ b_e1, float* __restrict__ out)
{
    extern __shared__ char smem[];
    const uint32_t sb = smem_u32(smem);

    const int tid = threadIdx.x, lane = tid & 31, wid = tid >> 5;
    const int wm = wid & 3;                 // warp row group (32 rows)
    const int wn = wid >> 2;                // warp col group (32 cols)
    const int m0 = blockIdx.y * BM;
    const int n0 = blockIdx.x * BN;
    const __half* Ap = g_Ah + (size_t)m0 * Hh;
    const __half* Bp = g_Bh + (size_t)n0 * Hh;

    float acc[2][4][4];
#pragma unroll
    for (int i = 0; i < 2; i++)
#pragma unroll
        for (int j = 0; j < 4; j++)
#pragma unroll
            for (int r = 0; r < 4; r++) acc[i][j][r] = 0.f;

    const int a_row = wm * 32 + (lane & 15);
    const int b_rowb = wn * 32 + (lane & 15);
    const int l_kc  = lane >> 4;

    load_stage(sb, Ap, Bp, 0, tid);
    CP_COMMIT();

    for (int t = 0; t < KT; t++) {
        if (t + 1 < KT) {
            load_stage(sb + (uint32_t)(((t + 1) & 1) * STG), Ap, Bp, t + 1, tid);
            CP_COMMIT();
            asm volatile("cp.async.wait_group 1;" ::: "memory");
        } else {
            asm volatile("cp.async.wait_group 0;" ::: "memory");
        }
        __syncthreads();

        const uint32_t Ab = sb + (uint32_t)((t & 1) * STG);
        const uint32_t Bbs = Ab + 16384;
#pragma unroll
        for (int ks = 0; ks < 4; ks++) {              // 4 k16-steps in BK=64
            const int kc = 2 * ks + l_kc;
            uint32_t a0r[4], a1r[4];
            {
                int r = a_row;
                LDSM4(a0r[0], a0r[1], a0r[2], a0r[3],
                      Ab + (uint32_t)(r * 128) + (uint32_t)((kc ^ (r & 7)) << 4));
                r = a_row + 16;
                LDSM4(a1r[0], a1r[1], a1r[2], a1r[3],
                      Ab + (uint32_t)(r * 128) + (uint32_t)((kc ^ (r & 7)) << 4));
            }
#pragma unroll
            for (int jg = 0; jg < 2; jg++) {          // 2 n16-groups = 4 n8-tiles
                int r = b_rowb + 16 * jg;
                uint32_t b0, b1, b2, b3;
                LDSM4(b0, b1, b2, b3,
                      Bbs + (uint32_t)(r * 128) + (uint32_t)((kc ^ (r & 7)) << 4));
                MMA16816(acc[0][2 * jg],     a0r[0], a0r[1], a0r[2], a0r[3], b0, b2);
                MMA16816(acc[0][2 * jg + 1], a0r[0], a0r[1], a0r[2], a0r[3], b1, b3);
                MMA16816(acc[1][2 * jg],     a1r[0], a1r[1], a1r[2], a1r[3], b0, b2);
                MMA16816(acc[1][2 * jg + 1], a1r[0], a1r[1], a1r[2], a1r[3], b1, b3);
            }
        }
        __syncthreads();
    }

    // ---- dump accumulators to smem [BM][EP_PITCH] ----
    float* eps = (float*)smem;
    const int rbase = wm * 32 + (lane >> 2);
    const int cbase = wn * 32 + (lane & 3) * 2;
#pragma unroll
    for (int i = 0; i < 2; i++)
#pragma unroll
        for (int j = 0; j < 4; j++) {
            int rr = rbase + i * 16;
            int cc = cbase + j * 8;
            *(float2*)&eps[rr * EP_PITCH + cc]       = make_float2(acc[i][j][0], acc[i][j][1]);
            *(float2*)&eps[(rr + 8) * EP_PITCH + cc] = make_float2(acc[i][j][2], acc[i][j][3]);
        }
    __syncthreads();

    // ---- epilogue ----
    const int blk = n0 >> 9;                 // 0 / 1 / 2
    const int cb  = n0 & 511;
    if (blk == 0) {
        const int r = tid >> 1, h = tid & 1;
        float s = 0.f;
#pragma unroll 8
        for (int c = 0; c < 32; c++) {
            int d = cb + h * 32 + c;
            s += fmaxf(eps[r * EP_PITCH + h * 32 + c] + __ldg(b_s1 + d), 0.f) * __ldg(w_s2 + d);
        }
        s += __shfl_xor_sync(0xffffffffu, s, 1);
        if (h == 0) atomicAdd(out + m0 + r, s);
    } else if (blk == 1) {
#pragma unroll 4
        for (int it = 0; it < 32; it++) {
            int idx = it * 256 + tid;            // 8192 = 128m x 64d
            int m = idx & 127, dl = idx >> 7;
            int d = cb + dl;
            float v = eps[m * EP_PITCH + dl] + __ldg(b_e1 + d);
            *(float2*)(g_aD + (size_t)d * (2 * Mm) + 2 * (m0 + m)) = make_float2(v, v);
        }
    } else {
#pragma unroll 4
        for (int it = 0; it < 32; it++) {
            int idx = it * 256 + tid;
            int m = idx & 127, dl = idx >> 7;
            g_cT[(size_t)(cb + dl) * Mm + m0 + m] = eps[m * EP_PITCH + dl];
        }
    }
}

// -------- end logits: packed f32x2, intra-CTA d-split, named-barrier halves --------
#define RELUFMA(acc, a2, c2, w2) \
    asm("{\n\t.reg .f32 lo, hi; .reg .b64 s, m;\n\t" \
        "add.rn.f32x2 s, %1, %2;\n\t" \
        "mov.b64 {lo, hi}, s;\n\t" \
        "max.f32 lo, lo, 0f00000000;\n\t" \
        "max.f32 hi, hi, 0f00000000;\n\t" \
        "mov.b64 m, {lo, hi};\n\t" \
        "fma.rn.f32x2 %0, m, %3, %0;\n\t}" \
        : "+l"(acc) : "l"(a2), "l"(c2), "l"(w2))

#define ADD2(acc, o) asm("add.rn.f32x2 %0, %0, %1;" : "+l"(acc) : "l"(o))
#define HBAR(id) asm volatile("bar.sync %0, 256;" :: "r"(id) : "memory")

__global__ __launch_bounds__(512) void end_kernel(
    const float* __restrict__ w_e2, const float* __restrict__ b_e2,
    float* __restrict__ out_end)
{
    extern __shared__ float sf[];
    // floats: [0,1024) W dup | half h at 1024 + h*12288: A 2x4096 then C 2x2048
    float2* Wsm = (float2*)sf;
    const uint32_t sb = smem_u32(sf);

    const int t  = threadIdx.x;
    const int ht = t >> 8;          // half id 0/1
    const int lt = t & 255;         // lane within half
    const int bz = blockIdx.z;
    const int i0 = blockIdx.y * 64, j0 = blockIdx.x * 64;
    const int mi = bz * Nn + i0, mj = bz * Nn + j0;

    { float w = w_e2[t]; Wsm[t] = make_float2(w, w); }   // half h writes/reads [256h,256h+256)

    const int tx = lt & 15;          // j-group: 4 j at tx*4
    const int ty = lt >> 4;          // i-group: 4 i at ty*4

    const float* Asrc0 = g_aD + 2 * mi;
    const float* Csrc0 = g_cT + mj;

    const uint32_t HB   = (uint32_t)(1024 + ht * 12288) * 4;  // byte offset of half base
    const float*   HBf  = sf + 1024 + ht * 12288;

    ull acc[4][2];
#pragma unroll
    for (int a = 0; a < 4; a++) { acc[a][0] = 0; acc[a][1] = 0; }

#define LOAD_CHUNK(ch, st) do { \
    const uint32_t _Ab = sb + HB + (uint32_t)((st) * 4096 * 4); \
    const uint32_t _Cb = sb + HB + (uint32_t)((8192 + (st) * 2048) * 4); \
    const float* _As = Asrc0 + (size_t)((ch) * 32) * 2048; \
    const float* _Cs = Csrc0 + (size_t)((ch) * 32) * 1024; \
    _Pragma("unroll") \
    for (int _i = 0; _i < 4; _i++) { \
        int _c = lt + _i * 256; \
        int _r = _c >> 5, _q = _c & 31; \
        CP16(_Ab + (uint32_t)(_r * 512 + _q * 16), _As + (size_t)_r * 2048 + _q * 4); \
    } \
    _Pragma("unroll") \
    for (int _i = 0; _i < 2; _i++) { \
        int _c = lt + _i * 256; \
        int _r = _c >> 4, _q = _c & 15; \
        CP16(_Cb + (uint32_t)(_r * 256 + _q * 16), _Cs + (size_t)_r * 1024 + _q * 4); \
    } \
} while (0)

    const int ch0 = ht * 8;
    LOAD_CHUNK(ch0, 0);
    CP_COMMIT();

    for (int ci = 0; ci < 8; ci++) {
        if (ci + 1 < 8) {
            LOAD_CHUNK(ch0 + ci + 1, (ci + 1) & 1);
            CP_COMMIT();
            asm volatile("cp.async.wait_group 1;" ::: "memory");
        } else {
            asm volatile("cp.async.wait_group 0;" ::: "memory");
        }
        HBAR(1 + ht);

        const int st = ci & 1;
        const float* Abuf = HBf + st * 4096;
        const float* Cbuf = HBf + 8192 + st * 2048;
        const int wb = (ch0 + ci) * 32;
#pragma unroll 8
        for (int dc = 0; dc < 32; dc++) {
            ull w2 = *(const ull*)&Wsm[wb + dc];
            const float* ar = Abuf + dc * 128 + ty * 8;
            ulonglong2 aP0 = *(const ulonglong2*)ar;          // dup pairs (i0),(i1)
            ulonglong2 aP1 = *(const ulonglong2*)(ar + 4);    // dup pairs (i2),(i3)
            ulonglong2 cP  = *(const ulonglong2*)(Cbuf + dc * 64 + tx * 4);  // (c0,c1),(c2,c3)
            RELUFMA(acc[0][0], aP0.x, cP.x, w2); RELUFMA(acc[0][1], aP0.x, cP.y, w2);
            RELUFMA(acc[1][0], aP0.y, cP.x, w2); RELUFMA(acc[1][1], aP0.y, cP.y, w2);
            RELUFMA(acc[2][0], aP1.x, cP.x, w2); RELUFMA(acc[2][1], aP1.x, cP.y, w2);
            RELUFMA(acc[3][0], aP1.y, cP.x, w2); RELUFMA(acc[3][1], aP1.y, cP.y, w2);
        }
        HBAR(1 + ht);
    }

    // ---- combine halves: half1 dumps accs into its (now idle) A stage0 buffer ----
    ull* cmb = (ull*)(sf + 1024 + 12288);       // 16KB region, half1's A stage0
    if (ht == 1) {
#pragma unroll
        for (int i = 0; i < 4; i++) {
            cmb[lt * 8 + 2 * i]     = acc[i][0];
            cmb[lt * 8 + 2 * i + 1] = acc[i][1];
        }
    }
    __syncthreads();

    if (ht == 0) {
        const float be = b_e2[0];
#pragma unroll
        for (int i = 0; i < 4; i++) {
            ADD2(acc[i][0], cmb[lt * 8 + 2 * i]);
            ADD2(acc[i][1], cmb[lt * 8 + 2 * i + 1]);
            float l0, h0, l1, h1;
            asm("mov.b64 {%0, %1}, %2;" : "=f"(l0), "=f"(h0) : "l"(acc[i][0]));
            asm("mov.b64 {%0, %1}, %2;" : "=f"(l1), "=f"(h1) : "l"(acc[i][1]));
            size_t r0 = (size_t)bz * Nn * Nn + (size_t)(i0 + ty * 4 + i) * Nn + j0 + tx * 4;
            *(float4*)(out_end + r0) = make_float4(l0 + be, h0 + be, l1 + be, h1 + be);
        }
    }
}

// -------- host --------
extern "C" void kernel_launch(void* const* d_in, const int* in_sizes, int n_in,
                              void* d_out, int out_size)
{
    (void)in_sizes; (void)n_in; (void)out_size;
    const float* emb  = (const float*)d_in[0];
    const float* W_s1 = (const float*)d_in[1];
    const float* b_s1 = (const float*)d_in[2];
    const float* w_s2 = (const float*)d_in[3];
    const float* b_s2 = (const float*)d_in[4];
    const float* W_e1 = (const float*)d_in[5];
    const float* b_e1 = (const float*)d_in[6];
    const float* w_e2 = (const float*)d_in[7];
    const float* b_e2 = (const float*)d_in[8];
    float* out = (float*)d_out;

    static bool attr_done = false;
    if (!attr_done) {
        cudaFuncSetAttribute(gemm_kernel, cudaFuncAttributeMaxDynamicSharedMemorySize, GEMM_SMEM);
        cudaFuncSetAttribute(end_kernel, cudaFuncAttributeMaxDynamicSharedMemorySize, END_SMEM);
        attr_done = true;
    }

    esplit_kernel<<<(Mm * Hh / 4) / 256, 256>>>(emb, b_s2, out);
    wsplit_kernel<<<dim3(NTOT / 32, Hh / 32), 256>>>(W_s1, W_e1);

    dim3 gg(NTOT / BN, Mm / BM);                  // 24 x 8 = 192 CTAs
    gemm_kernel<<<gg, 256, GEMM_SMEM>>>(b_s1, w_s2, b_e1, out);

    dim3 ge(Nn / 64, Nn / 64, Bb);                // 8 x 8 x 2 = 128 CTAs
    end_kernel<<<ge, 512, END_SMEM>>>(w_e2, b_e2, out + Mm);
}

// round 9
// speedup vs baseline: 1.1015x; 1.0374x over previous
#include <cuda_runtime.h>
#include <cuda_fp16.h>
#include <cstdint>

typedef unsigned long long ull;

#define Bb   2
#define Nn   512
#define Hh   1024
#define HDd  512
#define Mm   1024          // B*N rows
#define NTOT 1536          // fused GEMM output columns

// GEMM tiling
#define BM 128
#define BN 64
#define BK 64
#define KT (Hh / BK)             // 16 k-tiles
#define STG 24576                // A(16KB)+B(8KB) per stage
#define EP_PITCH 66              // epilogue smem pitch (floats)
#define GEMM_SMEM (2 * STG)      // 49152 >= 128*66*4 = 33792

// end kernel smem (floats): W dup 1024 | per group g (4): A 2x2048 + C 2x1024 (=6144)
#define END_SMEM ((1024 + 4 * 6144) * 4)   // 102400 bytes

// -------- scratch --------
__device__ __half g_Ah[Mm * Hh];            // emb in fp16
__device__ __half g_Bh[NTOT * Hh];          // weights transposed [n][k], fp16
__device__ float  g_aD[HDd * 2 * Mm];       // (emb@W1_start + b_e1)^T duplicated: [d][2m]=(v,v)
__device__ float  g_cT[HDd * Mm];           // (emb@W1_end)^T  [d][m]

// -------- PTX helpers --------
__device__ __forceinline__ uint32_t smem_u32(const void* p) {
    uint32_t a;
    asm("{ .reg .u64 t; cvta.to.shared.u64 t, %1; cvt.u32.u64 %0, t; }" : "=r"(a) : "l"(p));
    return a;
}
#define CP16(dst, src) \
    asm volatile("cp.async.cg.shared.global [%0], [%1], 16;" :: "r"(dst), "l"(src) : "memory")
#define CP_COMMIT() asm volatile("cp.async.commit_group;" ::: "memory")

#define LDSM4(r0, r1, r2, r3, a) \
    asm volatile("ldmatrix.sync.aligned.m8n8.x4.shared.b16 {%0,%1,%2,%3}, [%4];" \
        : "=r"(r0), "=r"(r1), "=r"(r2), "=r"(r3) : "r"(a))

#define MMA16816(d, a0, a1, a2, a3, b0, b1) \
    asm volatile("mma.sync.aligned.m16n8k16.row.col.f32.f16.f16.f32 " \
        "{%0,%1,%2,%3}, {%4,%5,%6,%7}, {%8,%9}, {%0,%1,%2,%3};" \
        : "+f"((d)[0]), "+f"((d)[1]), "+f"((d)[2]), "+f"((d)[3]) \
        : "r"(a0), "r"(a1), "r"(a2), "r"(a3), "r"(b0), "r"(b1))

// -------- prepass: emb -> fp16, plus start-logit output init --------
__global__ __launch_bounds__(256) void esplit_kernel(const float* __restrict__ emb,
                                                     const float* __restrict__ b_s2,
                                                     float* __restrict__ out) {
    int i = blockIdx.x * 256 + threadIdx.x;        // float4 index, 262144 total
    float4 v = ((const float4*)emb)[i];
    __half2* A = (__half2*)g_Ah;
    A[2 * i]     = __floats2half2_rn(v.x, v.y);
    A[2 * i + 1] = __floats2half2_rn(v.z, v.w);
    if (i < Mm) out[i] = b_s2[0];
}

// -------- prepass: transpose weights -> g_Bh[n][k] fp16 --------
__global__ __launch_bounds__(256) void wsplit_kernel(const float* __restrict__ W_s1,
                                                     const float* __restrict__ W_e1) {
    __shared__ float sm[32][33];
    const int n0 = blockIdx.x * 32, k0 = blockIdx.y * 32;
    const int t = threadIdx.x, c = t & 31, r = t >> 5;
#pragma unroll
    for (int p = 0; p < 4; p++) {
        int k = k0 + r + 8 * p, n = n0 + c;
        float v;
        if (n < 512)       v = W_s1[(size_t)k * 512 + n];
        else if (n < 1024) v = W_e1[(size_t)k * 512 + (n - 512)];
        else               v = W_e1[(size_t)(1024 + k) * 512 + (n - 1024)];
        sm[r + 8 * p][c] = v;   // sm[k_local][n_local]
    }
    __syncthreads();
#pragma unroll
    for (int p = 0; p < 4; p++) {
        int ln = r + 8 * p, lk = c;
        g_Bh[(size_t)(n0 + ln) * Hh + k0 + lk] = __float2half_rn(sm[lk][ln]);
    }
}

// -------- HMMA GEMM: C[1024,1536] = emb_fp16 @ [W_s1|W_e1a|W_e1b]_fp16 --------
__device__ __forceinline__ void load_stage(uint32_t abase, const __half* __restrict__ A,
                                           const __half* __restrict__ B, int kt, int tid) {
    const uint32_t bbase = abase + 16384;
#pragma unroll
    for (int i = 0; i < 4; i++) {
        int c = tid + i * 256;             // 1024 16B chunks for A (128 rows x 8)
        int row = c >> 3, kc = c & 7;
        uint32_t dst = abase + (uint32_t)(row * 128) + (uint32_t)((kc ^ (row & 7)) << 4);
        CP16(dst, A + (size_t)row * Hh + kt * BK + kc * 8);
    }
#pragma unroll
    for (int i = 0; i < 2; i++) {
        int c = tid + i * 256;             // 512 chunks for B (64 rows x 8)
        int row = c >> 3, kc = c & 7;
        uint32_t dst = bbase + (uint32_t)(row * 128) + (uint32_t)((kc ^ (row & 7)) << 4);
        CP16(dst, B + (size_t)row * Hh + kt * BK + kc * 8);
    }
}

__global__ __launch_bounds__(256, 2) void gemm_kernel(
    const float* __restrict__ b_s1, const float* __restrict__ w_s2,
    const float* __restrict__ b_e1, float* __restrict__ out)
{
    extern __shared__ char smem[];
    const uint32_t sb = smem_u32(smem);

    const int tid = threadIdx.x, lane = tid & 31, wid = tid >> 5;
    const int wm = wid & 3;                 // warp row group (32 rows)
    const int wn = wid >> 2;                // warp col group (32 cols)
    const int m0 = blockIdx.y * BM;
    const int n0 = blockIdx.x * BN;
    const __half* Ap = g_Ah + (size_t)m0 * Hh;
    const __half* Bp = g_Bh + (size_t)n0 * Hh;

    float acc[2][4][4];
#pragma unroll
    for (int i = 0; i < 2; i++)
#pragma unroll
        for (int j = 0; j < 4; j++)
#pragma unroll
            for (int r = 0; r < 4; r++) acc[i][j][r] = 0.f;

    const int a_row = wm * 32 + (lane & 15);
    const int b_rowb = wn * 32 + (lane & 15);
    const int l_kc  = lane >> 4;

    load_stage(sb, Ap, Bp, 0, tid);
    CP_COMMIT();

    for (int t = 0; t < KT; t++) {
        if (t + 1 < KT) {
            load_stage(sb + (uint32_t)(((t + 1) & 1) * STG), Ap, Bp, t + 1, tid);
            CP_COMMIT();
            asm volatile("cp.async.wait_group 1;" ::: "memory");
        } else {
            asm volatile("cp.async.wait_group 0;" ::: "memory");
        }
        __syncthreads();

        const uint32_t Ab = sb + (uint32_t)((t & 1) * STG);
        const uint32_t Bbs = Ab + 16384;
#pragma unroll
        for (int ks = 0; ks < 4; ks++) {              // 4 k16-steps in BK=64
            const int kc = 2 * ks + l_kc;
            uint32_t a0r[4], a1r[4];
            {
                int r = a_row;
                LDSM4(a0r[0], a0r[1], a0r[2], a0r[3],
                      Ab + (uint32_t)(r * 128) + (uint32_t)((kc ^ (r & 7)) << 4));
                r = a_row + 16;
                LDSM4(a1r[0], a1r[1], a1r[2], a1r[3],
                      Ab + (uint32_t)(r * 128) + (uint32_t)((kc ^ (r & 7)) << 4));
            }
#pragma unroll
            for (int jg = 0; jg < 2; jg++) {          // 2 n16-groups = 4 n8-tiles
                int r = b_rowb + 16 * jg;
                uint32_t b0, b1, b2, b3;
                LDSM4(b0, b1, b2, b3,
                      Bbs + (uint32_t)(r * 128) + (uint32_t)((kc ^ (r & 7)) << 4));
                MMA16816(acc[0][2 * jg],     a0r[0], a0r[1], a0r[2], a0r[3], b0, b2);
                MMA16816(acc[0][2 * jg + 1], a0r[0], a0r[1], a0r[2], a0r[3], b1, b3);
                MMA16816(acc[1][2 * jg],     a1r[0], a1r[1], a1r[2], a1r[3], b0, b2);
                MMA16816(acc[1][2 * jg + 1], a1r[0], a1r[1], a1r[2], a1r[3], b1, b3);
            }
        }
        __syncthreads();
    }

    // ---- dump accumulators to smem [BM][EP_PITCH] ----
    float* eps = (float*)smem;
    const int rbase = wm * 32 + (lane >> 2);
    const int cbase = wn * 32 + (lane & 3) * 2;
#pragma unroll
    for (int i = 0; i < 2; i++)
#pragma unroll
        for (int j = 0; j < 4; j++) {
            int rr = rbase + i * 16;
            int cc = cbase + j * 8;
            *(float2*)&eps[rr * EP_PITCH + cc]       = make_float2(acc[i][j][0], acc[i][j][1]);
            *(float2*)&eps[(rr + 8) * EP_PITCH + cc] = make_float2(acc[i][j][2], acc[i][j][3]);
        }
    __syncthreads();

    // ---- epilogue ----
    const int blk = n0 >> 9;                 // 0 / 1 / 2
    const int cb  = n0 & 511;
    if (blk == 0) {
        const int r = tid >> 1, h = tid & 1;
        float s = 0.f;
#pragma unroll 8
        for (int c = 0; c < 32; c++) {
            int d = cb + h * 32 + c;
            s += fmaxf(eps[r * EP_PITCH + h * 32 + c] + __ldg(b_s1 + d), 0.f) * __ldg(w_s2 + d);
        }
        s += __shfl_xor_sync(0xffffffffu, s, 1);
        if (h == 0) atomicAdd(out + m0 + r, s);
    } else if (blk == 1) {
#pragma unroll 4
        for (int it = 0; it < 32; it++) {
            int idx = it * 256 + tid;            // 8192 = 128m x 64d
            int m = idx & 127, dl = idx >> 7;
            int d = cb + dl;
            float v = eps[m * EP_PITCH + dl] + __ldg(b_e1 + d);
            *(float2*)(g_aD + (size_t)d * (2 * Mm) + 2 * (m0 + m)) = make_float2(v, v);
        }
    } else {
#pragma unroll 4
        for (int it = 0; it < 32; it++) {
            int idx = it * 256 + tid;
            int m = idx & 127, dl = idx >> 7;
            g_cT[(size_t)(cb + dl) * Mm + m0 + m] = eps[m * EP_PITCH + dl];
        }
    }
}

// -------- end logits: packed f32x2, 4-way intra-CTA d-split (1024 threads) --------
#define RELUFMA(acc, a2, c2, w2) \
    asm("{\n\t.reg .f32 lo, hi; .reg .b64 s, m;\n\t" \
        "add.rn.f32x2 s, %1, %2;\n\t" \
        "mov.b64 {lo, hi}, s;\n\t" \
        "max.f32 lo, lo, 0f00000000;\n\t" \
        "max.f32 hi, hi, 0f00000000;\n\t" \
        "mov.b64 m, {lo, hi};\n\t" \
        "fma.rn.f32x2 %0, m, %3, %0;\n\t}" \
        : "+l"(acc) : "l"(a2), "l"(c2), "l"(w2))

#define ADD2(acc, o) asm("add.rn.f32x2 %0, %0, %1;" : "+l"(acc) : "l"(o))
#define HBAR(id) asm volatile("bar.sync %0, 256;" :: "r"(id) : "memory")

__global__ __launch_bounds__(1024) void end_kernel(
    const float* __restrict__ w_e2, const float* __restrict__ b_e2,
    float* __restrict__ out_end)
{
    extern __shared__ float sf[];
    // floats: [0,1024) W dup | group g at 1024 + g*6144: A 2x2048 then C 2x1024
    float2* Wsm = (float2*)sf;
    const uint32_t sb = smem_u32(sf);

    const int t  = threadIdx.x;
    const int gq = t >> 8;          // group id 0..3 (d-quarter)
    const int lt = t & 255;         // lane within group
    const int bz = blockIdx.z;
    const int i0 = blockIdx.y * 64, j0 = blockIdx.x * 64;
    const int mi = bz * Nn + i0, mj = bz * Nn + j0;

    if (t < 512) { float w = w_e2[t]; Wsm[t] = make_float2(w, w); }

    const int tx = lt & 15;          // j-group: 4 j at tx*4
    const int ty = lt >> 4;          // i-group: 4 i at ty*4

    const float* Asrc0 = g_aD + 2 * mi;
    const float* Csrc0 = g_cT + mj;

    const uint32_t GB  = (uint32_t)(1024 + gq * 6144) * 4;   // byte offset of group base
    const float*   GBf = sf + 1024 + gq * 6144;

    ull acc[4][2];
#pragma unroll
    for (int a = 0; a < 4; a++) { acc[a][0] = 0; acc[a][1] = 0; }

// chunk = 16 d rows; A buf 16x128 (dup), C buf 16x64
#define LOAD_CHUNK(ch, st) do { \
    const uint32_t _Ab = sb + GB + (uint32_t)((st) * 2048 * 4); \
    const uint32_t _Cb = sb + GB + (uint32_t)((4096 + (st) * 1024) * 4); \
    const float* _As = Asrc0 + (size_t)((ch) * 16) * 2048; \
    const float* _Cs = Csrc0 + (size_t)((ch) * 16) * 1024; \
    _Pragma("unroll") \
    for (int _i = 0; _i < 2; _i++) { \
        int _c = lt + _i * 256; \
        int _r = _c >> 5, _q = _c & 31; \
        CP16(_Ab + (uint32_t)(_r * 512 + _q * 16), _As + (size_t)_r * 2048 + _q * 4); \
    } \
    { \
        int _r = lt >> 4, _q = lt & 15; \
        CP16(_Cb + (uint32_t)(_r * 256 + _q * 16), _Cs + (size_t)_r * 1024 + _q * 4); \
    } \
} while (0)

    const int ch0 = gq * 8;          // 8 chunks of 16 d per quarter
    LOAD_CHUNK(ch0, 0);
    CP_COMMIT();
    __syncthreads();                 // W visible to all groups; stage-0 loads in flight

    for (int ci = 0; ci < 8; ci++) {
        if (ci + 1 < 8) {
            LOAD_CHUNK(ch0 + ci + 1, (ci + 1) & 1);
            CP_COMMIT();
            asm volatile("cp.async.wait_group 1;" ::: "memory");
        } else {
            asm volatile("cp.async.wait_group 0;" ::: "memory");
        }
        HBAR(1 + gq);

        const int st = ci & 1;
        const float* Abuf = GBf + st * 2048;
        const float* Cbuf = GBf + 4096 + st * 1024;
        const int wb = (ch0 + ci) * 16;
#pragma unroll 8
        for (int dc = 0; dc < 16; dc++) {
            ull w2 = *(const ull*)&Wsm[wb + dc];
            const float* ar = Abuf + dc * 128 + ty * 8;
            ulonglong2 aP0 = *(const ulonglong2*)ar;          // dup pairs (i0),(i1)
            ulonglong2 aP1 = *(const ulonglong2*)(ar + 4);    // dup pairs (i2),(i3)
            ulonglong2 cP  = *(const ulonglong2*)(Cbuf + dc * 64 + tx * 4);  // (c0,c1),(c2,c3)
            RELUFMA(acc[0][0], aP0.x, cP.x, w2); RELUFMA(acc[0][1], aP0.x, cP.y, w2);
            RELUFMA(acc[1][0], aP0.y, cP.x, w2); RELUFMA(acc[1][1], aP0.y, cP.y, w2);
            RELUFMA(acc[2][0], aP1.x, cP.x, w2); RELUFMA(acc[2][1], aP1.x, cP.y, w2);
            RELUFMA(acc[3][0], aP1.y, cP.x, w2); RELUFMA(acc[3][1], aP1.y, cP.y, w2);
        }
        HBAR(1 + gq);
    }

    // ---- combine: groups 1-3 dump accs into their own (idle) A buffers ----
    if (gq != 0) {
        ull* dmp = (ull*)GBf;                // 2048*2 floats = 16KB region, need 16KB
#pragma unroll
        for (int i = 0; i < 4; i++) {
            dmp[lt * 8 + 2 * i]     = acc[i][0];
            dmp[lt * 8 + 2 * i + 1] = acc[i][1];
        }
    }
    __syncthreads();

    if (gq == 0) {
        const float be = b_e2[0];
#pragma unroll
        for (int i = 0; i < 4; i++) {
#pragma unroll
            for (int gg = 1; gg < 4; gg++) {
                const ull* dmp = (const ull*)(sf + 1024 + gg * 6144);
                ADD2(acc[i][0], dmp[lt * 8 + 2 * i]);
                ADD2(acc[i][1], dmp[lt * 8 + 2 * i + 1]);
            }
            float l0, h0, l1, h1;
            asm("mov.b64 {%0, %1}, %2;" : "=f"(l0), "=f"(h0) : "l"(acc[i][0]));
            asm("mov.b64 {%0, %1}, %2;" : "=f"(l1), "=f"(h1) : "l"(acc[i][1]));
            size_t r0 = (size_t)bz * Nn * Nn + (size_t)(i0 + ty * 4 + i) * Nn + j0 + tx * 4;
            *(float4*)(out_end + r0) = make_float4(l0 + be, h0 + be, l1 + be, h1 + be);
        }
    }
}

// -------- host --------
extern "C" void kernel_launch(void* const* d_in, const int* in_sizes, int n_in,
                              void* d_out, int out_size)
{
    (void)in_sizes; (void)n_in; (void)out_size;
    const float* emb  = (const float*)d_in[0];
    const float* W_s1 = (const float*)d_in[1];
    const float* b_s1 = (const float*)d_in[2];
    const float* w_s2 = (const float*)d_in[3];
    const float* b_s2 = (const float*)d_in[4];
    const float* W_e1 = (const float*)d_in[5];
    const float* b_e1 = (const float*)d_in[6];
    const float* w_e2 = (const float*)d_in[7];
    const float* b_e2 = (const float*)d_in[8];
    float* out = (float*)d_out;

    static bool attr_done = false;
    if (!attr_done) {
        cudaFuncSetAttribute(gemm_kernel, cudaFuncAttributeMaxDynamicSharedMemorySize, GEMM_SMEM);
        cudaFuncSetAttribute(end_kernel, cudaFuncAttributeMaxDynamicSharedMemorySize, END_SMEM);
        attr_done = true;
    }

    esplit_kernel<<<(Mm * Hh / 4) / 256, 256>>>(emb, b_s2, out);
    wsplit_kernel<<<dim3(NTOT / 32, Hh / 32), 256>>>(W_s1, W_e1);

    dim3 gg(NTOT / BN, Mm / BM);                  // 24 x 8 = 192 CTAs
    gemm_kernel<<<gg, 256, GEMM_SMEM>>>(b_s1, w_s2, b_e1, out);

    dim3 ge(Nn / 64, Nn / 64, Bb);                // 8 x 8 x 2 = 128 CTAs
    end_kernel<<<ge, 1024, END_SMEM>>>(w_e2, b_e2, out + Mm);
}

// round 10
// speedup vs baseline: 1.1092x; 1.0070x over previous
#include <cuda_runtime.h>
#include <cuda_fp16.h>
#include <cstdint>

typedef unsigned long long ull;

#define Bb   2
#define Nn   512
#define Hh   1024
#define HDd  512
#define Mm   1024          // B*N rows
#define NTOT 1536          // fused GEMM output columns

// GEMM tiling
#define BM 128
#define BN 64
#define BK 64
#define KT (Hh / BK)             // 16 k-tiles
#define STG 24576                // A(16KB)+B(8KB) per stage
#define EP_PITCH 66              // epilogue smem pitch (floats)
#define GEMM_SMEM (2 * STG)      // 49152 >= 128*66*4 = 33792

// end kernel smem (floats): W dup 1024 | per group g (4): A 2x2048 + C 2x1024 (=6144)
#define END_SMEM ((1024 + 4 * 6144) * 4)   // 102400 bytes

// -------- scratch --------
__device__ __half g_Ah[Mm * Hh];            // emb in fp16
__device__ __half g_Bh[NTOT * Hh];          // weights transposed [n][k], fp16
__device__ float  g_aD[HDd * 2 * Mm];       // (emb@W1_start + b_e1)^T duplicated: [d][2m]=(v,v)
__device__ float  g_cT[HDd * Mm];           // (emb@W1_end)^T  [d][m]

// -------- PTX helpers --------
__device__ __forceinline__ uint32_t smem_u32(const void* p) {
    uint32_t a;
    asm("{ .reg .u64 t; cvta.to.shared.u64 t, %1; cvt.u32.u64 %0, t; }" : "=r"(a) : "l"(p));
    return a;
}
#define CP16(dst, src) \
    asm volatile("cp.async.cg.shared.global [%0], [%1], 16;" :: "r"(dst), "l"(src) : "memory")
#define CP_COMMIT() asm volatile("cp.async.commit_group;" ::: "memory")

#define LDSM4(r0, r1, r2, r3, a) \
    asm volatile("ldmatrix.sync.aligned.m8n8.x4.shared.b16 {%0,%1,%2,%3}, [%4];" \
        : "=r"(r0), "=r"(r1), "=r"(r2), "=r"(r3) : "r"(a))

#define MMA16816(d, a0, a1, a2, a3, b0, b1) \
    asm volatile("mma.sync.aligned.m16n8k16.row.col.f32.f16.f16.f32 " \
        "{%0,%1,%2,%3}, {%4,%5,%6,%7}, {%8,%9}, {%0,%1,%2,%3};" \
        : "+f"((d)[0]), "+f"((d)[1]), "+f"((d)[2]), "+f"((d)[3]) \
        : "r"(a0), "r"(a1), "r"(a2), "r"(a3), "r"(b0), "r"(b1))

// -------- merged prepass: emb->fp16 + out init  |  weight transpose->fp16 --------
__global__ __launch_bounds__(256) void prep_kernel(const float* __restrict__ emb,
                                                   const float* __restrict__ W_s1,
                                                   const float* __restrict__ W_e1,
                                                   const float* __restrict__ b_s2,
                                                   float* __restrict__ out) {
    __shared__ float sm[32][33];
    if (blockIdx.x < 1024) {
        int i = blockIdx.x * 256 + threadIdx.x;        // float4 index, 262144 total
        float4 v = ((const float4*)emb)[i];
        __half2* A = (__half2*)g_Ah;
        A[2 * i]     = __floats2half2_rn(v.x, v.y);
        A[2 * i + 1] = __floats2half2_rn(v.z, v.w);
        if (i < Mm) out[i] = b_s2[0];
    } else {
        const int bx = blockIdx.x - 1024;              // 0..1535
        const int n0 = (bx % 48) * 32, k0 = (bx / 48) * 32;
        const int t = threadIdx.x, c = t & 31, r = t >> 5;
#pragma unroll
        for (int p = 0; p < 4; p++) {
            int k = k0 + r + 8 * p, n = n0 + c;
            float v;
            if (n < 512)       v = W_s1[(size_t)k * 512 + n];
            else if (n < 1024) v = W_e1[(size_t)k * 512 + (n - 512)];
            else               v = W_e1[(size_t)(1024 + k) * 512 + (n - 1024)];
            sm[r + 8 * p][c] = v;   // sm[k_local][n_local]
        }
        __syncthreads();
#pragma unroll
        for (int p = 0; p < 4; p++) {
            int ln = r + 8 * p, lk = c;
            g_Bh[(size_t)(n0 + ln) * Hh + k0 + lk] = __float2half_rn(sm[lk][ln]);
        }
    }
}

// -------- HMMA GEMM: C[1024,1536] = emb_fp16 @ [W_s1|W_e1a|W_e1b]_fp16 --------
__device__ __forceinline__ void load_stage(uint32_t abase, const __half* __restrict__ A,
                                           const __half* __restrict__ B, int kt, int tid) {
    const uint32_t bbase = abase + 16384;
#pragma unroll
    for (int i = 0; i < 4; i++) {
        int c = tid + i * 256;             // 1024 16B chunks for A (128 rows x 8)
        int row = c >> 3, kc = c & 7;
        uint32_t dst = abase + (uint32_t)(row * 128) + (uint32_t)((kc ^ (row & 7)) << 4);
        CP16(dst, A + (size_t)row * Hh + kt * BK + kc * 8);
    }
#pragma unroll
    for (int i = 0; i < 2; i++) {
        int c = tid + i * 256;             // 512 chunks for B (64 rows x 8)
        int row = c >> 3, kc = c & 7;
        uint32_t dst = bbase + (uint32_t)(row * 128) + (uint32_t)((kc ^ (row & 7)) << 4);
        CP16(dst, B + (size_t)row * Hh + kt * BK + kc * 8);
    }
}

__global__ __launch_bounds__(256, 2) void gemm_kernel(
    const float* __restrict__ b_s1, const float* __restrict__ w_s2,
    const float* __restrict__ b_e1, float* __restrict__ out)
{
    extern __shared__ char smem[];
    const uint32_t sb = smem_u32(smem);

    const int tid = threadIdx.x, lane = tid & 31, wid = tid >> 5;
    const int wm = wid & 3;                 // warp row group (32 rows)
    const int wn = wid >> 2;                // warp col group (32 cols)
    const int m0 = blockIdx.y * BM;
    const int n0 = blockIdx.x * BN;
    const __half* Ap = g_Ah + (size_t)m0 * Hh;
    const __half* Bp = g_Bh + (size_t)n0 * Hh;

    float acc[2][4][4];
#pragma unroll
    for (int i = 0; i < 2; i++)
#pragma unroll
        for (int j = 0; j < 4; j++)
#pragma unroll
            for (int r = 0; r < 4; r++) acc[i][j][r] = 0.f;

    const int a_row = wm * 32 + (lane & 15);
    const int b_rowb = wn * 32 + (lane & 15);
    const int l_kc  = lane >> 4;

    load_stage(sb, Ap, Bp, 0, tid);
    CP_COMMIT();

    for (int t = 0; t < KT; t++) {
        if (t + 1 < KT) {
            load_stage(sb + (uint32_t)(((t + 1) & 1) * STG), Ap, Bp, t + 1, tid);
            CP_COMMIT();
            asm volatile("cp.async.wait_group 1;" ::: "memory");
        } else {
            asm volatile("cp.async.wait_group 0;" ::: "memory");
        }
        __syncthreads();

        const uint32_t Ab = sb + (uint32_t)((t & 1) * STG);
        const uint32_t Bbs = Ab + 16384;
#pragma unroll
        for (int ks = 0; ks < 4; ks++) {              // 4 k16-steps in BK=64
            const int kc = 2 * ks + l_kc;
            uint32_t a0r[4], a1r[4];
            {
                int r = a_row;
                LDSM4(a0r[0], a0r[1], a0r[2], a0r[3],
                      Ab + (uint32_t)(r * 128) + (uint32_t)((kc ^ (r & 7)) << 4));
                r = a_row + 16;
                LDSM4(a1r[0], a1r[1], a1r[2], a1r[3],
                      Ab + (uint32_t)(r * 128) + (uint32_t)((kc ^ (r & 7)) << 4));
            }
#pragma unroll
            for (int jg = 0; jg < 2; jg++) {          // 2 n16-groups = 4 n8-tiles
                int r = b_rowb + 16 * jg;
                uint32_t b0, b1, b2, b3;
                LDSM4(b0, b1, b2, b3,
                      Bbs + (uint32_t)(r * 128) + (uint32_t)((kc ^ (r & 7)) << 4));
                MMA16816(acc[0][2 * jg],     a0r[0], a0r[1], a0r[2], a0r[3], b0, b2);
                MMA16816(acc[0][2 * jg + 1], a0r[0], a0r[1], a0r[2], a0r[3], b1, b3);
                MMA16816(acc[1][2 * jg],     a1r[0], a1r[1], a1r[2], a1r[3], b0, b2);
                MMA16816(acc[1][2 * jg + 1], a1r[0], a1r[1], a1r[2], a1r[3], b1, b3);
            }
        }
        __syncthreads();
    }

    // ---- dump accumulators to smem [BM][EP_PITCH] ----
    float* eps = (float*)smem;
    const int rbase = wm * 32 + (lane >> 2);
    const int cbase = wn * 32 + (lane & 3) * 2;
#pragma unroll
    for (int i = 0; i < 2; i++)
#pragma unroll
        for (int j = 0; j < 4; j++) {
            int rr = rbase + i * 16;
            int cc = cbase + j * 8;
            *(float2*)&eps[rr * EP_PITCH + cc]       = make_float2(acc[i][j][0], acc[i][j][1]);
            *(float2*)&eps[(rr + 8) * EP_PITCH + cc] = make_float2(acc[i][j][2], acc[i][j][3]);
        }
    __syncthreads();

    // ---- epilogue ----
    const int blk = n0 >> 9;                 // 0 / 1 / 2
    const int cb  = n0 & 511;
    if (blk == 0) {
        const int r = tid >> 1, h = tid & 1;
        float s = 0.f;
#pragma unroll 8
        for (int c = 0; c < 32; c++) {
            int d = cb + h * 32 + c;
            s += fmaxf(eps[r * EP_PITCH + h * 32 + c] + __ldg(b_s1 + d), 0.f) * __ldg(w_s2 + d);
        }
        s += __shfl_xor_sync(0xffffffffu, s, 1);
        if (h == 0) atomicAdd(out + m0 + r, s);
    } else if (blk == 1) {
#pragma unroll 4
        for (int it = 0; it < 32; it++) {
            int idx = it * 256 + tid;            // 8192 = 128m x 64d
            int m = idx & 127, dl = idx >> 7;
            int d = cb + dl;
            float v = eps[m * EP_PITCH + dl] + __ldg(b_e1 + d);
            *(float2*)(g_aD + (size_t)d * (2 * Mm) + 2 * (m0 + m)) = make_float2(v, v);
        }
    } else {
#pragma unroll 4
        for (int it = 0; it < 32; it++) {
            int idx = it * 256 + tid;
            int m = idx & 127, dl = idx >> 7;
            g_cT[(size_t)(cb + dl) * Mm + m0 + m] = eps[m * EP_PITCH + dl];
        }
    }
}

// -------- end logits: packed f32x2, 4-way d-split (512 thr, 128/group, 8i x 4j) --------
#define RELUFMA(acc, a2, c2, w2) \
    asm("{\n\t.reg .f32 lo, hi; .reg .b64 s, m;\n\t" \
        "add.rn.f32x2 s, %1, %2;\n\t" \
        "mov.b64 {lo, hi}, s;\n\t" \
        "max.f32 lo, lo, 0f00000000;\n\t" \
        "max.f32 hi, hi, 0f00000000;\n\t" \
        "mov.b64 m, {lo, hi};\n\t" \
        "fma.rn.f32x2 %0, m, %3, %0;\n\t}" \
        : "+l"(acc) : "l"(a2), "l"(c2), "l"(w2))

#define ADD2(acc, o) asm("add.rn.f32x2 %0, %0, %1;" : "+l"(acc) : "l"(o))
#define HBAR(id) asm volatile("bar.sync %0, 128;" :: "r"(id) : "memory")

__global__ __launch_bounds__(512) void end_kernel(
    const float* __restrict__ w_e2, const float* __restrict__ b_e2,
    float* __restrict__ out_end)
{
    extern __shared__ float sf[];
    // floats: [0,1024) W dup | group g at 1024 + g*6144: A 2x2048 then C 2x1024
    float2* Wsm = (float2*)sf;
    const uint32_t sb = smem_u32(sf);

    const int t  = threadIdx.x;
    const int gq = t >> 7;          // group id 0..3 (d-quarter)
    const int lt = t & 127;         // lane within group
    const int bz = blockIdx.z;
    const int i0 = blockIdx.y * 64, j0 = blockIdx.x * 64;
    const int mi = bz * Nn + i0, mj = bz * Nn + j0;

    { float w = w_e2[t]; Wsm[t] = make_float2(w, w); }   // t covers 0..511

    const int tx = lt & 15;          // j-group: 4 j at tx*4
    const int ty = lt >> 4;          // i-group: 8 i at ty*8

    const float* Asrc0 = g_aD + 2 * mi;
    const float* Csrc0 = g_cT + mj;

    const uint32_t GB  = (uint32_t)(1024 + gq * 6144) * 4;   // byte offset of group base
    const float*   GBf = sf + 1024 + gq * 6144;

    ull acc[8][2];
#pragma unroll
    for (int a = 0; a < 8; a++) { acc[a][0] = 0; acc[a][1] = 0; }

// chunk = 16 d rows; A buf 16x128 (dup), C buf 16x64; loaders: 128 threads
#define LOAD_CHUNK(ch, st) do { \
    const uint32_t _Ab = sb + GB + (uint32_t)((st) * 2048 * 4); \
    const uint32_t _Cb = sb + GB + (uint32_t)((4096 + (st) * 1024) * 4); \
    const float* _As = Asrc0 + (size_t)((ch) * 16) * 2048; \
    const float* _Cs = Csrc0 + (size_t)((ch) * 16) * 1024; \
    _Pragma("unroll") \
    for (int _i = 0; _i < 4; _i++) { \
        int _c = lt + _i * 128; \
        int _r = _c >> 5, _q = _c & 31; \
        CP16(_Ab + (uint32_t)(_r * 512 + _q * 16), _As + (size_t)_r * 2048 + _q * 4); \
    } \
    _Pragma("unroll") \
    for (int _i = 0; _i < 2; _i++) { \
        int _c = lt + _i * 128; \
        int _r = _c >> 4, _q = _c & 15; \
        CP16(_Cb + (uint32_t)(_r * 256 + _q * 16), _Cs + (size_t)_r * 1024 + _q * 4); \
    } \
} while (0)

    const int ch0 = gq * 8;          // 8 chunks of 16 d per quarter
    LOAD_CHUNK(ch0, 0);
    CP_COMMIT();
    __syncthreads();                 // W visible to all groups

    for (int ci = 0; ci < 8; ci++) {
        if (ci + 1 < 8) {
            LOAD_CHUNK(ch0 + ci + 1, (ci + 1) & 1);
            CP_COMMIT();
            asm volatile("cp.async.wait_group 1;" ::: "memory");
        } else {
            asm volatile("cp.async.wait_group 0;" ::: "memory");
        }
        HBAR(1 + gq);

        const int st = ci & 1;
        const float* Abuf = GBf + st * 2048;
        const float* Cbuf = GBf + 4096 + st * 1024;
        const int wb = (ch0 + ci) * 16;
#pragma unroll 8
        for (int dc = 0; dc < 16; dc++) {
            ull w2 = *(const ull*)&Wsm[wb + dc];
            const float* ar = Abuf + dc * 128 + ty * 16;          // 8 i dup = 16 floats
            ulonglong2 aP0 = *(const ulonglong2*)ar;              // (i0),(i1)
            ulonglong2 aP1 = *(const ulonglong2*)(ar + 4);        // (i2),(i3)
            ulonglong2 aP2 = *(const ulonglong2*)(ar + 8);        // (i4),(i5)
            ulonglong2 aP3 = *(const ulonglong2*)(ar + 12);       // (i6),(i7)
            ulonglong2 cP  = *(const ulonglong2*)(Cbuf + dc * 64 + tx * 4);  // (c0,c1),(c2,c3)
            RELUFMA(acc[0][0], aP0.x, cP.x, w2); RELUFMA(acc[0][1], aP0.x, cP.y, w2);
            RELUFMA(acc[1][0], aP0.y, cP.x, w2); RELUFMA(acc[1][1], aP0.y, cP.y, w2);
            RELUFMA(acc[2][0], aP1.x, cP.x, w2); RELUFMA(acc[2][1], aP1.x, cP.y, w2);
            RELUFMA(acc[3][0], aP1.y, cP.x, w2); RELUFMA(acc[3][1], aP1.y, cP.y, w2);
            RELUFMA(acc[4][0], aP2.x, cP.x, w2); RELUFMA(acc[4][1], aP2.x, cP.y, w2);
            RELUFMA(acc[5][0], aP2.y, cP.x, w2); RELUFMA(acc[5][1], aP2.y, cP.y, w2);
            RELUFMA(acc[6][0], aP3.x, cP.x, w2); RELUFMA(acc[6][1], aP3.x, cP.y, w2);
            RELUFMA(acc[7][0], aP3.y, cP.x, w2); RELUFMA(acc[7][1], aP3.y, cP.y, w2);
        }
        HBAR(1 + gq);
    }

    // ---- combine: groups 1-3 dump accs (i-major to avoid bank conflicts) ----
    if (gq != 0) {
        ull* dmp = (ull*)GBf;                // 16 x 128 ull = 16KB = A region (both stages)
#pragma unroll
        for (int i = 0; i < 8; i++) {
            dmp[(2 * i) * 128 + lt]     = acc[i][0];
            dmp[(2 * i + 1) * 128 + lt] = acc[i][1];
        }
    }
    __syncthreads();

    if (gq == 0) {
        const float be = b_e2[0];
#pragma unroll
        for (int i = 0; i < 8; i++) {
#pragma unroll
            for (int gg = 1; gg < 4; gg++) {
                const ull* dmp = (const ull*)(sf + 1024 + gg * 6144);
                ADD2(acc[i][0], dmp[(2 * i) * 128 + lt]);
                ADD2(acc[i][1], dmp[(2 * i + 1) * 128 + lt]);
            }
            float l0, h0, l1, h1;
            asm("mov.b64 {%0, %1}, %2;" : "=f"(l0), "=f"(h0) : "l"(acc[i][0]));
            asm("mov.b64 {%0, %1}, %2;" : "=f"(l1), "=f"(h1) : "l"(acc[i][1]));
            size_t r0 = (size_t)bz * Nn * Nn + (size_t)(i0 + ty * 8 + i) * Nn + j0 + tx * 4;
            *(float4*)(out_end + r0) = make_float4(l0 + be, h0 + be, l1 + be, h1 + be);
        }
    }
}

// -------- host --------
extern "C" void kernel_launch(void* const* d_in, const int* in_sizes, int n_in,
                              void* d_out, int out_size)
{
    (void)in_sizes; (void)n_in; (void)out_size;
    const float* emb  = (const float*)d_in[0];
    const float* W_s1 = (const float*)d_in[1];
    const float* b_s1 = (const float*)d_in[2];
    const float* w_s2 = (const float*)d_in[3];
    const float* b_s2 = (const float*)d_in[4];
    const float* W_e1 = (const float*)d_in[5];
    const float* b_e1 = (const float*)d_in[6];
    const float* w_e2 = (const float*)d_in[7];
    const float* b_e2 = (const float*)d_in[8];
    float* out = (float*)d_out;

    static bool attr_done = false;
    if (!attr_done) {
        cudaFuncSetAttribute(gemm_kernel, cudaFuncAttributeMaxDynamicSharedMemorySize, GEMM_SMEM);
        cudaFuncSetAttribute(end_kernel, cudaFuncAttributeMaxDynamicSharedMemorySize, END_SMEM);
        attr_done = true;
    }

    prep_kernel<<<2560, 256>>>(emb, W_s1, W_e1, b_s2, out);

    dim3 gg(NTOT / BN, Mm / BM);                  // 24 x 8 = 192 CTAs
    gemm_kernel<<<gg, 256, GEMM_SMEM>>>(b_s1, w_s2, b_e1, out);

    dim3 ge(Nn / 64, Nn / 64, Bb);                // 8 x 8 x 2 = 128 CTAs
    end_kernel<<<ge, 512, END_SMEM>>>(w_e2, b_e2, out + Mm);
}